// round 1
// baseline (speedup 1.0000x reference)
#include <cuda_runtime.h>

// CapsuleLayer dynamic routing, fully fused recompute (no hat materialization).
//   B=64 batch, N=4096 input caps, I=8 in-dim, C=32 out caps, D=16 out dim, 3 routings.
// Pass kernel (per routing iter): each CTA = (32 b's) x (32 n's). W staged in
// SMEM (xor-swizzled), hat recomputed in registers, softmax via 8-lane shfl,
// per-thread register accumulators for s[b,c,j], flushed to partial buffer.
// Reduce kernel: sum partials over 128 chunks, squash, update cumulative out.

#define B_ 64
#define N_ 4096
#define I_ 8
#define C_ 32
#define D_ 16
#define NB 32        // b per CTA
#define NCHUNK 32    // n per CTA
#define SUBN 4       // n per W smem stage (4 * 16KB = 64KB)
#define NCTA 128     // N_/NCHUNK
#define THREADS 256
#define OPAD 20      // padded D for O in smem (bank-friendly)

__device__ float g_part[(size_t)NCTA * B_ * C_ * D_];  // 16 MB partials [chunk][b][c][j]
__device__ float g_Ocum[B_ * C_ * D_];                 // cumulative sum of outs (for logits)

template<int ITER>
__global__ void __launch_bounds__(THREADS, 1)
caps_pass(const float* __restrict__ X, const float* __restrict__ W) {
    extern __shared__ float sm[];
    float* sW = sm;                               // SUBN*C_*D_*I_ = 16384 floats (64KB)
    float* sX = sm + SUBN * C_ * D_ * I_;         // NCHUNK*NB*I_  =  8192 floats (32KB)
    float* sO = sX + NCHUNK * NB * I_;            // NB*C_*OPAD    = 20480 floats (80KB, ITER>0)

    const int chunk = blockIdx.x;
    const int half  = blockIdx.y;
    const int n0 = chunk * NCHUNK;
    const int b0 = half * NB;
    const int tid = threadIdx.x;
    const int bl = tid >> 3;      // local b (0..31)
    const int cs = tid & 7;       // c slot; handles c = cs + 8k, k=0..3

    // ---- stage x chunk: sX[n][b][i] ----
    for (int idx = tid; idx < NCHUNK * NB * 2; idx += THREADS) {
        int bb  = idx >> 6;          // local b
        int rem = idx & 63;          // n*2 + ih
        float4 v = reinterpret_cast<const float4*>(X)
                       [(size_t)(b0 + bb) * (N_ * 2) + (size_t)n0 * 2 + rem];
        reinterpret_cast<float4*>(sX)[(rem >> 1) * (NB * 2) + bb * 2 + (rem & 1)] = v;
    }

    // ---- stage O (cumulative out) padded: sO[bl][c][OPAD] ----
    if (ITER > 0) {
        for (int row = tid; row < NB * C_; row += THREADS) {
            const float4* src = reinterpret_cast<const float4*>(g_Ocum) + (size_t)(b0 * C_ + row) * 4;
            float4* dst = reinterpret_cast<float4*>(sO + row * OPAD);
            dst[0] = src[0]; dst[1] = src[1]; dst[2] = src[2]; dst[3] = src[3];
        }
    }

    float acc[4][16];
    #pragma unroll
    for (int k = 0; k < 4; ++k)
        #pragma unroll
        for (int j = 0; j < 16; ++j) acc[k][j] = 0.f;

    for (int sub = 0; sub < NCHUNK / SUBN; ++sub) {
        __syncthreads();
        // ---- stage W sub-chunk, xor-swizzled: f4[r*32 + (c ^ (r&31))], r=(nn*16+j)*2+ih ----
        {
            const int nbase = n0 + sub * SUBN;
            for (int idx = tid; idx < C_ * SUBN * 32; idx += THREADS) {
                int c = idx >> 7;        // 0..31
                int r = idx & 127;       // 0..127
                float4 v = reinterpret_cast<const float4*>(W)
                               [(size_t)c * (N_ * 32) + (size_t)nbase * 32 + r];
                reinterpret_cast<float4*>(sW)[(r << 5) + (c ^ (r & 31))] = v;
            }
        }
        __syncthreads();

        #pragma unroll
        for (int nn = 0; nn < SUBN; ++nn) {
            const float4* xs = reinterpret_cast<const float4*>(sX) + ((sub * SUBN + nn) * NB + bl) * 2;
            const float4 x0 = xs[0], x1 = xs[1];

            float hat[4][16];
            float logit[4];
            #pragma unroll
            for (int k = 0; k < 4; ++k) {
                const int c = cs + 8 * k;
                #pragma unroll
                for (int j = 0; j < 16; ++j) {
                    const int r0 = nn * 32 + j * 2;   // r&31 == 2j (+ih), independent of nn
                    float4 w0 = reinterpret_cast<const float4*>(sW)[(r0 << 5)        + (c ^ ((2 * j)     & 31))];
                    float4 w1 = reinterpret_cast<const float4*>(sW)[((r0 + 1) << 5)  + (c ^ ((2 * j + 1) & 31))];
                    float h = x0.x * w0.x;
                    h = fmaf(x0.y, w0.y, h); h = fmaf(x0.z, w0.z, h); h = fmaf(x0.w, w0.w, h);
                    h = fmaf(x1.x, w1.x, h); h = fmaf(x1.y, w1.y, h);
                    h = fmaf(x1.z, w1.z, h); h = fmaf(x1.w, w1.w, h);
                    hat[k][j] = h;
                }
                if (ITER > 0) {
                    const float4* Ob = reinterpret_cast<const float4*>(sO + (bl * C_ + c) * OPAD);
                    float l = 0.f;
                    #pragma unroll
                    for (int jq = 0; jq < 4; ++jq) {
                        float4 o = Ob[jq];
                        l = fmaf(o.x, hat[k][4 * jq + 0], l);
                        l = fmaf(o.y, hat[k][4 * jq + 1], l);
                        l = fmaf(o.z, hat[k][4 * jq + 2], l);
                        l = fmaf(o.w, hat[k][4 * jq + 3], l);
                    }
                    logit[k] = l;
                }
            }

            if (ITER == 0) {
                // uniform coupling 1/32: accumulate raw hat, scale at flush
                #pragma unroll
                for (int k = 0; k < 4; ++k)
                    #pragma unroll
                    for (int j = 0; j < 16; ++j) acc[k][j] += hat[k][j];
            } else {
                // softmax over 32 c's: 4 local + 8-lane shfl tree (lanes of same b)
                float m = fmaxf(fmaxf(logit[0], logit[1]), fmaxf(logit[2], logit[3]));
                m = fmaxf(m, __shfl_xor_sync(0xffffffffu, m, 1));
                m = fmaxf(m, __shfl_xor_sync(0xffffffffu, m, 2));
                m = fmaxf(m, __shfl_xor_sync(0xffffffffu, m, 4));
                float e0 = __expf(logit[0] - m), e1 = __expf(logit[1] - m);
                float e2 = __expf(logit[2] - m), e3 = __expf(logit[3] - m);
                float s = (e0 + e1) + (e2 + e3);
                s += __shfl_xor_sync(0xffffffffu, s, 1);
                s += __shfl_xor_sync(0xffffffffu, s, 2);
                s += __shfl_xor_sync(0xffffffffu, s, 4);
                const float inv = __fdividef(1.f, s);
                const float cf[4] = {e0 * inv, e1 * inv, e2 * inv, e3 * inv};
                #pragma unroll
                for (int k = 0; k < 4; ++k)
                    #pragma unroll
                    for (int j = 0; j < 16; ++j)
                        acc[k][j] = fmaf(cf[k], hat[k][j], acc[k][j]);
            }
        }
    }

    // ---- flush partial sums ----
    const float scale = (ITER == 0) ? (1.f / 32.f) : 1.f;
    const int b = b0 + bl;
    #pragma unroll
    for (int k = 0; k < 4; ++k) {
        const int c = cs + 8 * k;
        float4* dst = reinterpret_cast<float4*>(g_part) + ((size_t)(chunk * B_ + b) * C_ + c) * 4;
        #pragma unroll
        for (int jq = 0; jq < 4; ++jq) {
            dst[jq] = make_float4(acc[k][4 * jq + 0] * scale, acc[k][4 * jq + 1] * scale,
                                  acc[k][4 * jq + 2] * scale, acc[k][4 * jq + 3] * scale);
        }
    }
}

// mode 0: g_Ocum = squash(s); mode 1: g_Ocum += squash(s); mode 2: out = squash(s)
__global__ void caps_reduce(float* __restrict__ out, int mode) {
    const int idx = blockIdx.x * 256 + threadIdx.x;   // 0..32767 = (b*32+c)*16+j
    float s0 = 0.f, s1 = 0.f, s2 = 0.f, s3 = 0.f;
    #pragma unroll 4
    for (int k = 0; k < NCTA; k += 4) {
        s0 += g_part[(size_t)k       * (B_ * C_ * D_) + idx];
        s1 += g_part[(size_t)(k + 1) * (B_ * C_ * D_) + idx];
        s2 += g_part[(size_t)(k + 2) * (B_ * C_ * D_) + idx];
        s3 += g_part[(size_t)(k + 3) * (B_ * C_ * D_) + idx];
    }
    const float s = (s0 + s1) + (s2 + s3);
    float sq = s * s;   // reduce over j (16 consecutive lanes)
    sq += __shfl_xor_sync(0xffffffffu, sq, 1);
    sq += __shfl_xor_sync(0xffffffffu, sq, 2);
    sq += __shfl_xor_sync(0xffffffffu, sq, 4);
    sq += __shfl_xor_sync(0xffffffffu, sq, 8);
    const float v = s * (sq / ((1.f + sq) * sqrtf(sq + 1e-7f)));
    if (mode == 0)      g_Ocum[idx] = v;
    else if (mode == 1) g_Ocum[idx] += v;
    else                out[idx] = v;
}

extern "C" void kernel_launch(void* const* d_in, const int* in_sizes, int n_in,
                              void* d_out, int out_size) {
    const float* X = (const float*)d_in[0];
    const float* W = (const float*)d_in[1];
    // defensive: pick by element count (inputs: 2,097,152 ; W: 16,777,216)
    if (n_in >= 2 && in_sizes[0] != B_ * N_ * I_) {
        X = (const float*)d_in[1];
        W = (const float*)d_in[0];
    }
    float* out = (float*)d_out;

    const int smem0  = (SUBN * C_ * D_ * I_ + NCHUNK * NB * I_) * 4;          // 98304 B
    const int smem12 = smem0 + NB * C_ * OPAD * 4;                             // 180224 B
    cudaFuncSetAttribute(caps_pass<0>, cudaFuncAttributeMaxDynamicSharedMemorySize, smem0);
    cudaFuncSetAttribute(caps_pass<1>, cudaFuncAttributeMaxDynamicSharedMemorySize, smem12);
    cudaFuncSetAttribute(caps_pass<2>, cudaFuncAttributeMaxDynamicSharedMemorySize, smem12);

    dim3 grid(NCTA, 2);
    caps_pass<0><<<grid, THREADS, smem0 >>>(X, W);
    caps_reduce <<<128, 256>>>(out, 0);
    caps_pass<1><<<grid, THREADS, smem12>>>(X, W);
    caps_reduce <<<128, 256>>>(out, 1);
    caps_pass<2><<<grid, THREADS, smem12>>>(X, W);
    caps_reduce <<<128, 256>>>(out, 2);
}